// round 7
// baseline (speedup 1.0000x reference)
#include <cuda_runtime.h>
#include <cstdint>

#define NN     512
#define NMAT   8          // B*R = 2*4
#define TILE   64
#define CH     32         // c-chunk per smem stage
#define NSTG   8          // 256 c's per unit / CH
#define STR    34         // smem row stride (floats): 136B rows, 8B-aligned, bank step 2
#define NUNITS 1024       // m(8) * ta(8) * ti(8) * cs(2)
#define GRID   444        // 148 SMs * 3 resident blocks

__device__ float    g_P[NMAT * NN * NN];  // packed masked probabilities [m][row][col]
__device__ double   g_acc;                // sum over units of (512*sum_p [cs0] - sum_min)
__device__ unsigned g_unit;               // dynamic work counter
__device__ unsigned g_done;               // finished-block counter

__device__ __forceinline__ float sigmoidf_(float x) {
    return 1.0f / (1.0f + __expf(-x));
}

// Pass 1: sigmoid + mask, transpose [B,N,N,R] -> 8 contiguous [N,N] matrices.
__global__ void __launch_bounds__(256) prep_kernel(const float* __restrict__ logits,
                                                   const int* __restrict__ mask) {
    int idx = blockIdx.x * 256 + threadIdx.x;      // over B*N*N = 524288 (exact fit)
    int b   = idx >> 18;
    int rem = idx & (NN * NN - 1);
    int a   = rem >> 9;
    int i   = rem & (NN - 1);

    float4 v = reinterpret_cast<const float4*>(logits)[idx];   // 4 relations packed
    float mm = ((mask[b * NN + a] > 0) && (mask[b * NN + i] > 0)) ? 1.0f : 0.0f;

    int base = a * NN + i;
    int moff = b * 4 * NN * NN;
    g_P[moff + 0 * NN * NN + base] = mm * sigmoidf_(v.x);
    g_P[moff + 1 * NN * NN + base] = mm * sigmoidf_(v.y);
    g_P[moff + 2 * NN * NN + base] = mm * sigmoidf_(v.z);
    g_P[moff + 3 * NN * NN + base] = mm * sigmoidf_(v.w);
}

// Stage one CH-wide slab of X (rows a0..) and Y (rows i0..) via cp.async (8B).
__device__ __forceinline__ void stage_cp(const float* __restrict__ P,
                                         int a0, int i0, int cb,
                                         float* Xb, float* Yb, int tid) {
    #pragma unroll
    for (int k = 0; k < 4; ++k) {
        int idx = k * 256 + tid;
        int row = idx >> 4;
        int ch8 = idx & 15;
        const float* sx = P + (a0 + row) * NN + cb + ch8 * 2;
        const float* sy = P + (i0 + row) * NN + cb + ch8 * 2;
        unsigned dx = (unsigned)__cvta_generic_to_shared(Xb + row * STR + ch8 * 2);
        unsigned dy = (unsigned)__cvta_generic_to_shared(Yb + row * STR + ch8 * 2);
        asm volatile("cp.async.ca.shared.global [%0], [%1], 8;\n\t"
                     "cp.async.ca.shared.global [%2], [%3], 8;"
                     :: "r"(dx), "l"(sx), "r"(dy), "l"(sy));
    }
    asm volatile("cp.async.commit_group;");
}

// Pass 2 (persistent, dynamic units, cp.async double-buffered, fused finalize):
// unit = (m, a-tile, i-tile, c-half). Per unit: 64x64 pairs x 256 c's.
// s_unit = (cs==0 ? 512*sum(p) : 0) - sum_{a,i,c} min(p_ai, P[a,c]*P[i,c])
__global__ void __launch_bounds__(256, 3) trans_kernel(float* __restrict__ out) {
    __shared__ float Xs[2][TILE * STR];
    __shared__ float Ys[2][TILE * STR];
    __shared__ unsigned s_u;
    __shared__ double  red[8];

    int tid = threadIdx.x;
    int tx = tid & 15, ty = tid >> 4;

    double local = 0.0;

    for (;;) {
        __syncthreads();                    // protect s_u / smem from previous unit
        if (tid == 0) s_u = atomicAdd(&g_unit, 1u);
        __syncthreads();
        unsigned u = s_u;
        if (u >= NUNITS) break;

        int cs = u & 1;
        int ti = (u >> 1) & 7;
        int ta = (u >> 4) & 7;
        int m  = u >> 7;

        const float* __restrict__ P = g_P + m * NN * NN;
        int a0 = ta * TILE, i0 = ti * TILE, c0 = cs * 256;

        // Kick off stage 0 immediately; p-loads below overlap with it.
        stage_cp(P, a0, i0, c0, Xs[0], Ys[0], tid);

        // p block: 16 scalars per thread (strided 4x4, coalesced across tx)
        float p[16];
        #pragma unroll
        for (int ja = 0; ja < 4; ++ja)
            #pragma unroll
            for (int ji = 0; ji < 4; ++ji)
                p[ja * 4 + ji] = P[(a0 + ty + 16 * ja) * NN + (i0 + tx + 16 * ji)];

        if (cs == 0) {
            float ps = 0.0f;
            #pragma unroll
            for (int k = 0; k < 16; ++k) ps += p[k];
            local += 512.0 * (double)ps;
        }

        // 8 packed accumulators: acc[(ja>>1)*4 + ji] takes ja and ja+1 tiles.
        unsigned long long acc[8];
        #pragma unroll
        for (int k = 0; k < 8; ++k) acc[k] = 0ull;   // f32x2 {0,0}

        for (int s = 0; s < NSTG; ++s) {
            asm volatile("cp.async.wait_group 0;" ::: "memory");
            __syncthreads();               // stage s visible; buf[(s+1)&1] free
            if (s < NSTG - 1)
                stage_cp(P, a0, i0, c0 + (s + 1) * CH, Xs[(s + 1) & 1], Ys[(s + 1) & 1], tid);

            const float* Xb = Xs[s & 1];
            const float* Yb = Ys[s & 1];
            #pragma unroll 4
            for (int cc = 0; cc < CH / 2; ++cc) {
                unsigned long long x2[4], y2[4];
                #pragma unroll
                for (int j = 0; j < 4; ++j)
                    x2[j] = *reinterpret_cast<const unsigned long long*>(
                                &Xb[(ty + 16 * j) * STR + 2 * cc]);
                #pragma unroll
                for (int j = 0; j < 4; ++j)
                    y2[j] = *reinterpret_cast<const unsigned long long*>(
                                &Yb[(tx + 16 * j) * STR + 2 * cc]);
                #pragma unroll
                for (int jp = 0; jp < 2; ++jp)          // ja pair: {2jp, 2jp+1}
                    #pragma unroll
                    for (int ji = 0; ji < 4; ++ji) {
                        unsigned long long qa, qb;
                        asm("mul.rn.f32x2 %0, %1, %2;"
                            : "=l"(qa) : "l"(x2[2 * jp]), "l"(y2[ji]));
                        asm("mul.rn.f32x2 %0, %1, %2;"
                            : "=l"(qb) : "l"(x2[2 * jp + 1]), "l"(y2[ji]));
                        asm("{\n\t"
                            ".reg .f32 l, h;\n\t"
                            "mov.b64 {l, h}, %1;\n\t"
                            "min.f32 l, l, %2;\n\t"
                            "min.f32 h, h, %2;\n\t"
                            "mov.b64 %0, {l, h};\n\t"
                            "}"
                            : "=l"(qa) : "l"(qa), "f"(p[2 * jp * 4 + ji]));
                        asm("{\n\t"
                            ".reg .f32 l, h;\n\t"
                            "mov.b64 {l, h}, %1;\n\t"
                            "min.f32 l, l, %2;\n\t"
                            "min.f32 h, h, %2;\n\t"
                            "mov.b64 %0, {l, h};\n\t"
                            "}"
                            : "=l"(qb) : "l"(qb), "f"(p[(2 * jp + 1) * 4 + ji]));
                        asm("add.rn.f32x2 %0, %1, %2;"
                            : "=l"(qa) : "l"(qa), "l"(qb));
                        asm("add.rn.f32x2 %0, %1, %2;"
                            : "=l"(acc[jp * 4 + ji]) : "l"(acc[jp * 4 + ji]), "l"(qa));
                    }
            }
        }

        float s = 0.0f;
        #pragma unroll
        for (int k = 0; k < 8; ++k) {
            float2 f = *reinterpret_cast<float2*>(&acc[k]);
            s += f.x + f.y;
        }
        local -= (double)s;
    }

    // Block reduction of per-thread doubles, then one atomicAdd per block.
    #pragma unroll
    for (int o = 16; o; o >>= 1) local += __shfl_xor_sync(0xffffffffu, local, o);
    if ((tid & 31) == 0) red[tid >> 5] = local;
    __syncthreads();
    if (tid < 32) {
        double bsum = (tid < 8) ? red[tid] : 0.0;
        #pragma unroll
        for (int o = 4; o; o >>= 1) bsum += __shfl_xor_sync(0xffffffffu, bsum, o);
        if (tid == 0) {
            atomicAdd(&g_acc, bsum);
            __threadfence();
            unsigned d = atomicAdd(&g_done, 1u);
            if (d == GRID - 1) {               // last block: finalize + reset for replay
                out[0] = (float)(g_acc * 0.125);
                g_acc  = 0.0;
                g_done = 0u;
                g_unit = 0u;
            }
        }
    }
}

extern "C" void kernel_launch(void* const* d_in, const int* in_sizes, int n_in,
                              void* d_out, int out_size) {
    const float* logits = (const float*)d_in[0];   // [2,512,512,4] fp32
    const int*   masks  = (const int*)d_in[1];     // [2,512] int32
    (void)in_sizes; (void)n_in; (void)out_size;

    prep_kernel<<<(2 * NN * NN) / 256, 256>>>(logits, masks);   // 2048 blocks
    trans_kernel<<<GRID, 256>>>((float*)d_out);                 // persistent
}

// round 10
// speedup vs baseline: 1.1069x; 1.1069x over previous
#include <cuda_runtime.h>
#include <cstdint>

#define NN     512
#define NMAT   8          // B*R = 2*4
#define TILE   64
#define CH     32         // c-chunk per smem stage
#define STR    34         // smem row stride (floats): 136B rows, 8B-aligned, bank step 2
#define NUNITS 2048       // m(8) * ta(8) * ti(8) * cs(4); 128 c's per unit = 4 stages
#define GRID   296        // 148 SMs * 2 resident blocks; units/block = 6.92

__device__ float    g_P [NMAT * NN * NN]; // masked probabilities [m][row][col]
__device__ float    g_Pn[NMAT * NN * NN]; // negated copy
__device__ double   g_acc;
__device__ unsigned g_done;

__device__ __forceinline__ float sigmoidf_(float x) {
    return 1.0f / (1.0f + __expf(-x));
}

// Pass 1: sigmoid + mask, transpose [B,N,N,R] -> 8 contiguous [N,N] matrices (+ negated copy).
__global__ void __launch_bounds__(256) prep_kernel(const float* __restrict__ logits,
                                                   const int* __restrict__ mask) {
    int idx = blockIdx.x * 256 + threadIdx.x;      // over B*N*N = 524288 (exact fit)
    int b   = idx >> 18;
    int rem = idx & (NN * NN - 1);
    int a   = rem >> 9;
    int i   = rem & (NN - 1);

    float4 v = reinterpret_cast<const float4*>(logits)[idx];
    float mm = ((mask[b * NN + a] > 0) && (mask[b * NN + i] > 0)) ? 1.0f : 0.0f;

    int base = a * NN + i;
    int moff = b * 4 * NN * NN;
    float p0 = mm * sigmoidf_(v.x);
    float p1 = mm * sigmoidf_(v.y);
    float p2 = mm * sigmoidf_(v.z);
    float p3 = mm * sigmoidf_(v.w);
    g_P [moff + 0 * NN * NN + base] =  p0;
    g_P [moff + 1 * NN * NN + base] =  p1;
    g_P [moff + 2 * NN * NN + base] =  p2;
    g_P [moff + 3 * NN * NN + base] =  p3;
    g_Pn[moff + 0 * NN * NN + base] = -p0;
    g_Pn[moff + 1 * NN * NN + base] = -p1;
    g_Pn[moff + 2 * NN * NN + base] = -p2;
    g_Pn[moff + 3 * NN * NN + base] = -p3;
}

__device__ __forceinline__ void unit_coords(unsigned u, int& m, int& a0, int& i0, int& c0) {
    c0 = (int)(u & 3u) * 128;
    i0 = (int)((u >> 2) & 7u) * TILE;
    a0 = (int)((u >> 5) & 7u) * TILE;
    m  = (int)(u >> 8);
}

// Stage one CH-wide slab: X rows (a0..) from g_Pn (negated), Y rows (i0..) from g_P.
__device__ __forceinline__ void stage_cp(int m, int a0, int i0, int cb,
                                         float* Xb, float* Yb, int tid) {
    const float* Pn = g_Pn + m * NN * NN;
    const float* Pp = g_P  + m * NN * NN;
    #pragma unroll
    for (int k = 0; k < 4; ++k) {
        int idx = k * 256 + tid;
        int row = idx >> 4;
        int ch8 = idx & 15;
        const float* sx = Pn + (a0 + row) * NN + cb + ch8 * 2;
        const float* sy = Pp + (i0 + row) * NN + cb + ch8 * 2;
        unsigned dx = (unsigned)__cvta_generic_to_shared(Xb + row * STR + ch8 * 2);
        unsigned dy = (unsigned)__cvta_generic_to_shared(Yb + row * STR + ch8 * 2);
        asm volatile("cp.async.ca.shared.global [%0], [%1], 8;\n\t"
                     "cp.async.ca.shared.global [%2], [%3], 8;"
                     :: "r"(dx), "l"(sx), "r"(dy), "l"(sy));
    }
    asm volatile("cp.async.commit_group;");
}

// Pass 2: persistent, static stride-GRID unit assignment, continuous double buffer.
// unit = (m, ta, ti, c-quarter): 64x64 pairs x 128 c's (4 stages of 32).
// Sum_{a,i,c} relu(p_ai - x_ac*y_ic) accumulated directly (relu-form, no correction).
__global__ void __launch_bounds__(256, 2) trans_kernel(float* __restrict__ out) {
    __shared__ float Xs[2][TILE * STR];
    __shared__ float Ys[2][TILE * STR];
    __shared__ double red[8];

    int tid = threadIdx.x;
    int tx = tid & 15, ty = tid >> 4;
    unsigned bid = blockIdx.x;

    double local = 0.0;
    int par = 0;                         // buffer parity, flows across units

    // Prologue: prefetch first unit's stage 0.
    if (bid < NUNITS) {
        int m, a0, i0, c0;
        unit_coords(bid, m, a0, i0, c0);
        stage_cp(m, a0, i0, c0, Xs[0], Ys[0], tid);
    }

    for (unsigned u = bid; u < NUNITS; u += GRID) {
        int m, a0, i0, c0;
        unit_coords(u, m, a0, i0, c0);
        const float* __restrict__ Pp = g_P + m * NN * NN;

        // p block packed as {p,p} pairs: 16 per thread (strided 4x4)
        unsigned long long p2[16];
        #pragma unroll
        for (int ja = 0; ja < 4; ++ja)
            #pragma unroll
            for (int ji = 0; ji < 4; ++ji) {
                float pv = Pp[(a0 + ty + 16 * ja) * NN + (i0 + tx + 16 * ji)];
                asm("mov.b64 %0, {%1, %1};" : "=l"(p2[ja * 4 + ji]) : "f"(pv));
            }

        unsigned long long acc[8];
        #pragma unroll
        for (int k = 0; k < 8; ++k) acc[k] = 0ull;

        #pragma unroll
        for (int s = 0; s < 4; ++s) {
            asm volatile("cp.async.wait_group 0;" ::: "memory");
            __syncthreads();               // stage visible; other buffer free
            // Prefetch next stage (same unit, or next unit's stage 0).
            if (s < 3) {
                stage_cp(m, a0, i0, c0 + (s + 1) * CH, Xs[par ^ 1], Ys[par ^ 1], tid);
            } else if (u + GRID < NUNITS) {
                int m2, a2, i2, c2;
                unit_coords(u + GRID, m2, a2, i2, c2);
                stage_cp(m2, a2, i2, c2, Xs[par ^ 1], Ys[par ^ 1], tid);
            }

            const float* Xb = Xs[par];
            const float* Yb = Ys[par];
            #pragma unroll 4
            for (int cc = 0; cc < CH / 2; ++cc) {
                unsigned long long x2[4], y2[4];
                #pragma unroll
                for (int j = 0; j < 4; ++j)
                    x2[j] = *reinterpret_cast<const unsigned long long*>(
                                &Xb[(ty + 16 * j) * STR + 2 * cc]);
                #pragma unroll
                for (int j = 0; j < 4; ++j)
                    y2[j] = *reinterpret_cast<const unsigned long long*>(
                                &Yb[(tx + 16 * j) * STR + 2 * cc]);
                #pragma unroll
                for (int jp = 0; jp < 2; ++jp)          // ja pair: {2jp, 2jp+1}
                    #pragma unroll
                    for (int ji = 0; ji < 4; ++ji) {
                        unsigned long long qa, qb;
                        // q = p - x*y  (x stored negated)
                        asm("fma.rn.f32x2 %0, %1, %2, %3;"
                            : "=l"(qa) : "l"(x2[2 * jp]), "l"(y2[ji]),
                              "l"(p2[2 * jp * 4 + ji]));
                        asm("fma.rn.f32x2 %0, %1, %2, %3;"
                            : "=l"(qb) : "l"(x2[2 * jp + 1]), "l"(y2[ji]),
                              "l"(p2[(2 * jp + 1) * 4 + ji]));
                        asm("{\n\t"
                            ".reg .f32 l, h;\n\t"
                            "mov.b64 {l, h}, %1;\n\t"
                            "max.f32 l, l, 0f00000000;\n\t"
                            "max.f32 h, h, 0f00000000;\n\t"
                            "mov.b64 %0, {l, h};\n\t"
                            "}"
                            : "=l"(qa) : "l"(qa));
                        asm("{\n\t"
                            ".reg .f32 l, h;\n\t"
                            "mov.b64 {l, h}, %1;\n\t"
                            "max.f32 l, l, 0f00000000;\n\t"
                            "max.f32 h, h, 0f00000000;\n\t"
                            "mov.b64 %0, {l, h};\n\t"
                            "}"
                            : "=l"(qb) : "l"(qb));
                        asm("add.rn.f32x2 %0, %1, %2;"
                            : "=l"(qa) : "l"(qa), "l"(qb));
                        asm("add.rn.f32x2 %0, %1, %2;"
                            : "=l"(acc[jp * 4 + ji]) : "l"(acc[jp * 4 + ji]), "l"(qa));
                    }
            }
            par ^= 1;
        }

        float s = 0.0f;
        #pragma unroll
        for (int k = 0; k < 8; ++k) {
            float2 f = *reinterpret_cast<float2*>(&acc[k]);
            s += f.x + f.y;
        }
        local += (double)s;
    }

    // Block reduction of per-thread doubles, then one atomicAdd per block.
    #pragma unroll
    for (int o = 16; o; o >>= 1) local += __shfl_xor_sync(0xffffffffu, local, o);
    if ((tid & 31) == 0) red[tid >> 5] = local;
    __syncthreads();
    if (tid < 32) {
        double bsum = (tid < 8) ? red[tid] : 0.0;
        #pragma unroll
        for (int o = 4; o; o >>= 1) bsum += __shfl_xor_sync(0xffffffffu, bsum, o);
        if (tid == 0) {
            atomicAdd(&g_acc, bsum);
            __threadfence();
            unsigned d = atomicAdd(&g_done, 1u);
            if (d == GRID - 1) {               // last block: finalize + reset for replay
                out[0] = (float)(g_acc * 0.125);
                g_acc  = 0.0;
                g_done = 0u;
            }
        }
    }
}

extern "C" void kernel_launch(void* const* d_in, const int* in_sizes, int n_in,
                              void* d_out, int out_size) {
    const float* logits = (const float*)d_in[0];   // [2,512,512,4] fp32
    const int*   masks  = (const int*)d_in[1];     // [2,512] int32
    (void)in_sizes; (void)n_in; (void)out_size;

    prep_kernel<<<(2 * NN * NN) / 256, 256>>>(logits, masks);   // 2048 blocks
    trans_kernel<<<GRID, 256>>>((float*)d_out);                 // persistent
}

// round 15
// speedup vs baseline: 1.6372x; 1.4791x over previous
#include <cuda_runtime.h>
#include <cuda_fp16.h>
#include <cstdint>

#define NN     512
#define NMAT   8          // B*R = 2*4
#define TILE   64
#define CH     64         // c's per smem stage (fp16)
#define STRH   68         // smem row stride in halves: 136B rows, 8B-aligned, bank step 2
#define NUNITS 2048       // m(8)*ta(8)*ti(8)*cs(4); 128 c's per unit = 2 stages
#define GRID   296        // 148 SMs * 2 resident blocks

__device__ __half   g_Hn[NMAT * NN * NN]; // -P/16  (fp16)
__device__ __half   g_Hy[NMAT * NN * NN]; //  P     (fp16)
__device__ __half   g_Hp[NMAT * NN * NN]; //  P/16  (fp16)
__device__ double   g_acc;
__device__ unsigned g_done;

__device__ __forceinline__ float sigmoidf_(float x) {
    return 1.0f / (1.0f + __expf(-x));
}

// Pass 1: sigmoid + mask, transpose [B,N,N,R] -> 8 contiguous [N,N] fp16 matrices
// in three flavors: -P/16 (X operand), P (Y operand), P/16 (p operand).
__global__ void __launch_bounds__(256) prep_kernel(const float* __restrict__ logits,
                                                   const int* __restrict__ mask) {
    int idx = blockIdx.x * 256 + threadIdx.x;      // over B*N*N = 524288 (exact fit)
    int b   = idx >> 18;
    int rem = idx & (NN * NN - 1);
    int a   = rem >> 9;
    int i   = rem & (NN - 1);

    float4 v = reinterpret_cast<const float4*>(logits)[idx];
    float mm = ((mask[b * NN + a] > 0) && (mask[b * NN + i] > 0)) ? 1.0f : 0.0f;

    float p[4];
    p[0] = mm * sigmoidf_(v.x);
    p[1] = mm * sigmoidf_(v.y);
    p[2] = mm * sigmoidf_(v.z);
    p[3] = mm * sigmoidf_(v.w);

    int base = a * NN + i;
    int moff = b * 4 * NN * NN;
    #pragma unroll
    for (int r = 0; r < 4; ++r) {
        int o = moff + r * NN * NN + base;
        g_Hn[o] = __float2half_rn(-p[r] * 0.0625f);
        g_Hy[o] = __float2half_rn( p[r]);
        g_Hp[o] = __float2half_rn( p[r] * 0.0625f);
    }
}

__device__ __forceinline__ void unit_coords(unsigned u, int& m, int& a0, int& i0, int& c0) {
    c0 = (int)(u & 3u) * 128;
    i0 = (int)((u >> 2) & 7u) * TILE;
    a0 = (int)((u >> 5) & 7u) * TILE;
    m  = (int)(u >> 8);
}

// Stage one CH-wide fp16 slab: X rows (a0..) from g_Hn, Y rows (i0..) from g_Hy.
// 64 rows x 64 c x 2B = 128B/row = 16 8B-chunks; 4 chunks/thread/array.
__device__ __forceinline__ void stage_cp(int m, int a0, int i0, int cb,
                                         __half* Xb, __half* Yb, int tid) {
    const __half* Xn = g_Hn + m * NN * NN;
    const __half* Yy = g_Hy + m * NN * NN;
    #pragma unroll
    for (int k = 0; k < 4; ++k) {
        int idx = k * 256 + tid;
        int row = idx >> 4;
        int ch8 = idx & 15;               // 8B chunk = 4 halves
        const __half* sx = Xn + (a0 + row) * NN + cb + ch8 * 4;
        const __half* sy = Yy + (i0 + row) * NN + cb + ch8 * 4;
        unsigned dx = (unsigned)__cvta_generic_to_shared(Xb + row * STRH + ch8 * 4);
        unsigned dy = (unsigned)__cvta_generic_to_shared(Yb + row * STRH + ch8 * 4);
        asm volatile("cp.async.ca.shared.global [%0], [%1], 8;\n\t"
                     "cp.async.ca.shared.global [%2], [%3], 8;"
                     :: "r"(dx), "l"(sx), "r"(dy), "l"(sy));
    }
    asm volatile("cp.async.commit_group;");
}

// Pass 2: persistent, static stride-GRID units, continuous double buffer.
// unit = (m, ta, ti, c-quarter): 64x64 pairs x 128 c's (2 stages of 64).
// Per triple: relu(p/16 - (x/16)*y) fused into ONE fma.rn.relu.f16x2 (x stored
// negated+prescaled). Stage-windowed fp16 accumulation, fp16 tree flush -> f32.
__global__ void __launch_bounds__(256, 2) trans_kernel(float* __restrict__ out) {
    __shared__ __half Xs[2][TILE * STRH];
    __shared__ __half Ys[2][TILE * STRH];
    __shared__ double red[8];

    int tid = threadIdx.x;
    int tx = tid & 15, ty = tid >> 4;
    unsigned bid = blockIdx.x;

    float lf = 0.0f;                     // per-thread f32 accumulator (prescaled)
    int par = 0;                         // buffer parity, flows across units

    // Prologue: prefetch first unit's stage 0.
    if (bid < NUNITS) {
        int m, a0, i0, c0;
        unit_coords(bid, m, a0, i0, c0);
        stage_cp(m, a0, i0, c0, Xs[0], Ys[0], tid);
    }

    for (unsigned u = bid; u < NUNITS; u += GRID) {
        int m, a0, i0, c0;
        unit_coords(u, m, a0, i0, c0);
        const __half* __restrict__ Hp = g_Hp + m * NN * NN;

        // p operand packed as {p/16, p/16} fp16x2: 16 per thread (strided 4x4)
        unsigned p2h[16];
        #pragma unroll
        for (int ja = 0; ja < 4; ++ja)
            #pragma unroll
            for (int ji = 0; ji < 4; ++ji) {
                unsigned hv = (unsigned)__half_as_ushort(
                    Hp[(a0 + ty + 16 * ja) * NN + (i0 + tx + 16 * ji)]);
                p2h[ja * 4 + ji] = hv | (hv << 16);
            }

        #pragma unroll
        for (int s = 0; s < 2; ++s) {
            asm volatile("cp.async.wait_group 0;" ::: "memory");
            __syncthreads();               // stage visible; other buffer free
            if (s == 0) {
                stage_cp(m, a0, i0, c0 + CH, Xs[par ^ 1], Ys[par ^ 1], tid);
            } else if (u + GRID < NUNITS) {
                int m2, a2, i2, c2;
                unit_coords(u + GRID, m2, a2, i2, c2);
                stage_cp(m2, a2, i2, c2, Xs[par ^ 1], Ys[par ^ 1], tid);
            }

            const __half* Xb = Xs[par];
            const __half* Yb = Ys[par];

            unsigned acc16[16];            // per-tile fp16x2 window (this stage)
            #pragma unroll
            for (int k = 0; k < 16; ++k) acc16[k] = 0u;

            #pragma unroll 8
            for (int cc4 = 0; cc4 < CH / 4; ++cc4) {   // 4 c's per step
                unsigned xlo[4], xhi[4], ylo[4], yhi[4];
                #pragma unroll
                for (int j = 0; j < 4; ++j) {
                    uint2 v = *reinterpret_cast<const uint2*>(
                        Xb + (ty + 16 * j) * STRH + cc4 * 4);
                    xlo[j] = v.x; xhi[j] = v.y;
                }
                #pragma unroll
                for (int j = 0; j < 4; ++j) {
                    uint2 v = *reinterpret_cast<const uint2*>(
                        Yb + (tx + 16 * j) * STRH + cc4 * 4);
                    ylo[j] = v.x; yhi[j] = v.y;
                }
                #pragma unroll
                for (int ja = 0; ja < 4; ++ja)
                    #pragma unroll
                    for (int ji = 0; ji < 4; ++ji) {
                        int k = ja * 4 + ji;
                        unsigned q0, q1;
                        asm("fma.rn.relu.f16x2 %0, %1, %2, %3;"
                            : "=r"(q0) : "r"(xlo[ja]), "r"(ylo[ji]), "r"(p2h[k]));
                        asm("fma.rn.relu.f16x2 %0, %1, %2, %3;"
                            : "=r"(q1) : "r"(xhi[ja]), "r"(yhi[ji]), "r"(p2h[k]));
                        asm("add.rn.f16x2 %0, %1, %2;"
                            : "=r"(q0) : "r"(q0), "r"(q1));
                        asm("add.rn.f16x2 %0, %1, %2;"
                            : "=r"(acc16[k]) : "r"(acc16[k]), "r"(q0));
                    }
            }

            // Flush stage window: fp16 tree 16 -> 1, then to f32.
            unsigned t[8];
            #pragma unroll
            for (int k = 0; k < 8; ++k)
                asm("add.rn.f16x2 %0, %1, %2;"
                    : "=r"(t[k]) : "r"(acc16[k]), "r"(acc16[k + 8]));
            #pragma unroll
            for (int k = 0; k < 4; ++k)
                asm("add.rn.f16x2 %0, %1, %2;"
                    : "=r"(t[k]) : "r"(t[k]), "r"(t[k + 4]));
            asm("add.rn.f16x2 %0, %1, %2;" : "=r"(t[0]) : "r"(t[0]), "r"(t[1]));
            asm("add.rn.f16x2 %0, %1, %2;" : "=r"(t[2]) : "r"(t[2]), "r"(t[3]));
            asm("add.rn.f16x2 %0, %1, %2;" : "=r"(t[0]) : "r"(t[0]), "r"(t[2]));
            __half2 h2 = *reinterpret_cast<__half2*>(&t[0]);
            float2 f2 = __half22float2(h2);
            lf += f2.x + f2.y;

            par ^= 1;
        }
    }

    // Per-thread f32 -> double once; block reduction; one atomicAdd per block.
    double local = (double)lf;
    #pragma unroll
    for (int o = 16; o; o >>= 1) local += __shfl_xor_sync(0xffffffffu, local, o);
    if ((tid & 31) == 0) red[tid >> 5] = local;
    __syncthreads();
    if (tid < 32) {
        double bsum = (tid < 8) ? red[tid] : 0.0;
        #pragma unroll
        for (int o = 4; o; o >>= 1) bsum += __shfl_xor_sync(0xffffffffu, bsum, o);
        if (tid == 0) {
            atomicAdd(&g_acc, bsum);
            __threadfence();
            unsigned d = atomicAdd(&g_done, 1u);
            if (d == GRID - 1) {               // last block: finalize + reset for replay
                // undo 1/16 prescale (x16), divide by B*R (/8)  => x2
                out[0] = (float)(g_acc * 2.0);
                g_acc  = 0.0;
                g_done = 0u;
            }
        }
    }
}

extern "C" void kernel_launch(void* const* d_in, const int* in_sizes, int n_in,
                              void* d_out, int out_size) {
    const float* logits = (const float*)d_in[0];   // [2,512,512,4] fp32
    const int*   masks  = (const int*)d_in[1];     // [2,512] int32
    (void)in_sizes; (void)n_in; (void)out_size;

    prep_kernel<<<(2 * NN * NN) / 256, 256>>>(logits, masks);   // 2048 blocks
    trans_kernel<<<GRID, 256>>>((float*)d_out);                 // persistent
}